// round 1
// baseline (speedup 1.0000x reference)
#include <cuda_runtime.h>

// Problem constants
#define BB   2
#define SDIM 2048
#define DD   1024
#define HH   16
#define DKK  64

// Scratch (device globals; no allocations allowed)
__device__ float g_q[BB * SDIM * DD];
__device__ float g_k[BB * SDIM * DD];
__device__ float g_v[BB * SDIM * DD];
__device__ float g_ctx[BB * SDIM * DD];

// ---------------------------------------------------------------------------
// Generic fp32 SGEMM: C = A(MxK) * B(KxN), row-major, M%128==0, N%128==0, K%8==0
// 128x128 block tile, K-tile 8, 256 threads, 8x8 per-thread microtile.
// ---------------------------------------------------------------------------
__global__ __launch_bounds__(256, 2)
void sgemm_nn(const float* __restrict__ A, const float* __restrict__ B,
              float* __restrict__ C, int M, int N, int K)
{
    __shared__ float As[8][128];
    __shared__ float Bs[8][128];

    const int tid  = threadIdx.x;
    const int arow = tid >> 1,  acol = (tid & 1) << 2;   // A tile load: 128 rows x 8 k
    const int brow = tid >> 5,  bcol = (tid & 31) << 2;  // B tile load: 8 k x 128 cols
    const int trow = (tid >> 4) << 3;                    // microtile row base
    const int tcol = (tid & 15) << 3;                    // microtile col base

    const float* Ap = A + (size_t)(blockIdx.y * 128 + arow) * K + acol;
    const float* Bp = B + (size_t)brow * N + blockIdx.x * 128 + bcol;

    float acc[8][8] = {};

    for (int k0 = 0; k0 < K; k0 += 8) {
        float4 a4 = *(const float4*)Ap;
        float4 b4 = *(const float4*)Bp;
        As[acol + 0][arow] = a4.x;
        As[acol + 1][arow] = a4.y;
        As[acol + 2][arow] = a4.z;
        As[acol + 3][arow] = a4.w;
        *(float4*)&Bs[brow][bcol] = b4;
        __syncthreads();

        #pragma unroll
        for (int k = 0; k < 8; ++k) {
            float a[8], b[8];
            *(float4*)&a[0] = *(const float4*)&As[k][trow];
            *(float4*)&a[4] = *(const float4*)&As[k][trow + 4];
            *(float4*)&b[0] = *(const float4*)&Bs[k][tcol];
            *(float4*)&b[4] = *(const float4*)&Bs[k][tcol + 4];
            #pragma unroll
            for (int i = 0; i < 8; ++i)
                #pragma unroll
                for (int j = 0; j < 8; ++j)
                    acc[i][j] = fmaf(a[i], b[j], acc[i][j]);
        }
        __syncthreads();

        Ap += 8;
        Bp += (size_t)8 * N;
    }

    float* Cp = C + (size_t)(blockIdx.y * 128 + trow) * N + blockIdx.x * 128 + tcol;
    #pragma unroll
    for (int i = 0; i < 8; ++i) {
        *(float4*)&Cp[(size_t)i * N]     = make_float4(acc[i][0], acc[i][1], acc[i][2], acc[i][3]);
        *(float4*)&Cp[(size_t)i * N + 4] = make_float4(acc[i][4], acc[i][5], acc[i][6], acc[i][7]);
    }
}

// ---------------------------------------------------------------------------
// scores[b,h,i,j] = (q_bh[i] . k_bh[j]) / 8 + mask[b,i,j] * (-1e9)
// NT GEMM per (b,h), K = DK = 64. Tiles with bx > by are fully causal-masked:
// skipped entirely (softmax zero-fills them).
// ---------------------------------------------------------------------------
__global__ __launch_bounds__(256, 2)
void scores_kernel(const float* __restrict__ q, const float* __restrict__ k,
                   const float* __restrict__ mask, float* __restrict__ attn)
{
    const int bx = blockIdx.x;     // key tile
    const int by = blockIdx.y;     // query tile
    if (bx > by) return;           // strictly upper tile: fully masked
    const int z = blockIdx.z;      // b*H + h
    const int b = z >> 4;
    const int h = z & 15;

    __shared__ float As[8][128];
    __shared__ float Bs[8][128];

    const int tid  = threadIdx.x;
    const int lrow = tid >> 1, lcol = (tid & 1) << 2;
    const int trow = (tid >> 4) << 3;
    const int tcol = (tid & 15) << 3;

    const float* Ap = q + (size_t)(b * SDIM + by * 128 + lrow) * DD + h * DKK + lcol;
    const float* Bp = k + (size_t)(b * SDIM + bx * 128 + lrow) * DD + h * DKK + lcol;

    float acc[8][8] = {};

    for (int k0 = 0; k0 < DKK; k0 += 8) {
        float4 a4 = *(const float4*)Ap;
        float4 b4 = *(const float4*)Bp;
        As[lcol + 0][lrow] = a4.x;  As[lcol + 1][lrow] = a4.y;
        As[lcol + 2][lrow] = a4.z;  As[lcol + 3][lrow] = a4.w;
        Bs[lcol + 0][lrow] = b4.x;  Bs[lcol + 1][lrow] = b4.y;
        Bs[lcol + 2][lrow] = b4.z;  Bs[lcol + 3][lrow] = b4.w;
        __syncthreads();

        #pragma unroll
        for (int kk = 0; kk < 8; ++kk) {
            float a[8], bb[8];
            *(float4*)&a[0]  = *(const float4*)&As[kk][trow];
            *(float4*)&a[4]  = *(const float4*)&As[kk][trow + 4];
            *(float4*)&bb[0] = *(const float4*)&Bs[kk][tcol];
            *(float4*)&bb[4] = *(const float4*)&Bs[kk][tcol + 4];
            #pragma unroll
            for (int i = 0; i < 8; ++i)
                #pragma unroll
                for (int j = 0; j < 8; ++j)
                    acc[i][j] = fmaf(a[i], bb[j], acc[i][j]);
        }
        __syncthreads();

        Ap += 8;
        Bp += 8;
    }

    float*       Op = attn + ((size_t)z * SDIM + by * 128 + trow) * SDIM + bx * 128 + tcol;
    const float* Mp = mask + ((size_t)b * SDIM + by * 128 + trow) * SDIM + bx * 128 + tcol;
    #pragma unroll
    for (int i = 0; i < 8; ++i) {
        #pragma unroll
        for (int j4 = 0; j4 < 8; j4 += 4) {
            float4 m4 = *(const float4*)&Mp[(size_t)i * SDIM + j4];
            float4 o4;
            o4.x = acc[i][j4 + 0] * 0.125f - 1e9f * m4.x;
            o4.y = acc[i][j4 + 1] * 0.125f - 1e9f * m4.y;
            o4.z = acc[i][j4 + 2] * 0.125f - 1e9f * m4.z;
            o4.w = acc[i][j4 + 3] * 0.125f - 1e9f * m4.w;
            *(float4*)&Op[(size_t)i * SDIM + j4] = o4;
        }
    }
}

// ---------------------------------------------------------------------------
// Row softmax in place over the computed prefix [0, L); zero-fill [L, S).
// L = next tile boundary past row index i (everything beyond is fully masked).
// ---------------------------------------------------------------------------
__global__ __launch_bounds__(256)
void softmax_kernel(float* __restrict__ attn)
{
    __shared__ float srow[SDIM];
    __shared__ float redmax[8];
    __shared__ float redsum[8];

    const int r   = blockIdx.x;          // (b*H + h)*S + i
    const int i   = r & (SDIM - 1);
    const int L   = ((i >> 7) + 1) << 7; // computed prefix length
    const int tid = threadIdx.x;
    float* row = attn + (size_t)r * SDIM;

    float m = -3.4e38f;
    for (int j = tid; j < L; j += 256) {
        float x = row[j];
        srow[j] = x;
        m = fmaxf(m, x);
    }
    #pragma unroll
    for (int o = 16; o; o >>= 1) m = fmaxf(m, __shfl_xor_sync(0xffffffffu, m, o));
    if ((tid & 31) == 0) redmax[tid >> 5] = m;
    __syncthreads();
    if (tid == 0) {
        float t = redmax[0];
        #pragma unroll
        for (int w = 1; w < 8; ++w) t = fmaxf(t, redmax[w]);
        redmax[0] = t;
    }
    __syncthreads();
    const float M = redmax[0];

    float s = 0.f;
    for (int j = tid; j < L; j += 256) {
        float e = __expf(srow[j] - M);
        srow[j] = e;
        s += e;
    }
    #pragma unroll
    for (int o = 16; o; o >>= 1) s += __shfl_xor_sync(0xffffffffu, s, o);
    if ((tid & 31) == 0) redsum[tid >> 5] = s;
    __syncthreads();
    if (tid == 0) {
        float t = 0.f;
        #pragma unroll
        for (int w = 0; w < 8; ++w) t += redsum[w];
        redsum[0] = t;
    }
    __syncthreads();
    const float inv = 1.f / redsum[0];

    for (int j = tid; j < L; j += 256) row[j] = srow[j] * inv;
    for (int j = L + tid; j < SDIM; j += 256) row[j] = 0.f;
}

// ---------------------------------------------------------------------------
// context[b,i,h*64+c] = sum_j attn[b,h,i,j] * v[b,j,h*64+c]
// NN GEMM per (b,h): M=S, N=64, K truncated at row-tile bound (causal zeros).
// ---------------------------------------------------------------------------
__global__ __launch_bounds__(256, 2)
void context_kernel(const float* __restrict__ attn, const float* __restrict__ v,
                    float* __restrict__ ctx)
{
    const int z = blockIdx.z;
    const int b = z >> 4;
    const int h = z & 15;
    const int i0 = blockIdx.y * 128;

    __shared__ float As[8][128];
    __shared__ float Bs[8][64];

    const int tid  = threadIdx.x;
    const int arow = tid >> 1,  acol = (tid & 1) << 2;
    const int brow = tid >> 5,  bcol = (tid & 31) << 1;
    const int trow = (tid >> 4) << 3;
    const int tcol = (tid & 15) << 2;

    const float* Ap = attn + ((size_t)z * SDIM + i0 + arow) * SDIM + acol;
    const float* Bp = v + ((size_t)(b * SDIM) + brow) * DD + h * DKK + bcol;

    const int Kend = i0 + 128;  // attn row i is zero beyond its tile bound
    float acc[8][4] = {};

    for (int k0 = 0; k0 < Kend; k0 += 8) {
        float4 a4 = *(const float4*)Ap;
        float2 b2 = *(const float2*)Bp;
        As[acol + 0][arow] = a4.x;
        As[acol + 1][arow] = a4.y;
        As[acol + 2][arow] = a4.z;
        As[acol + 3][arow] = a4.w;
        Bs[brow][bcol]     = b2.x;
        Bs[brow][bcol + 1] = b2.y;
        __syncthreads();

        #pragma unroll
        for (int kk = 0; kk < 8; ++kk) {
            float a[8], bb[4];
            *(float4*)&a[0]  = *(const float4*)&As[kk][trow];
            *(float4*)&a[4]  = *(const float4*)&As[kk][trow + 4];
            *(float4*)&bb[0] = *(const float4*)&Bs[kk][tcol];
            #pragma unroll
            for (int i = 0; i < 8; ++i)
                #pragma unroll
                for (int j = 0; j < 4; ++j)
                    acc[i][j] = fmaf(a[i], bb[j], acc[i][j]);
        }
        __syncthreads();

        Ap += 8;
        Bp += (size_t)8 * DD;
    }

    #pragma unroll
    for (int i = 0; i < 8; ++i) {
        float* Cp = ctx + ((size_t)(b * SDIM) + i0 + trow + i) * DD + h * DKK + tcol;
        *(float4*)Cp = make_float4(acc[i][0], acc[i][1], acc[i][2], acc[i][3]);
    }
}

// ---------------------------------------------------------------------------
extern "C" void kernel_launch(void* const* d_in, const int* in_sizes, int n_in,
                              void* d_out, int out_size)
{
    const float* query = (const float*)d_in[0];
    const float* key   = (const float*)d_in[1];
    const float* value = (const float*)d_in[2];
    const float* mask  = (const float*)d_in[3];
    const float* wq    = (const float*)d_in[4];
    const float* wk    = (const float*)d_in[5];
    const float* wv    = (const float*)d_in[6];
    const float* wo    = (const float*)d_in[7];

    float* out  = (float*)d_out;
    float* attn = out + (size_t)BB * SDIM * DD;  // attn_weights follow output

    float *q, *k, *v, *ctx;
    cudaGetSymbolAddress((void**)&q,   g_q);
    cudaGetSymbolAddress((void**)&k,   g_k);
    cudaGetSymbolAddress((void**)&v,   g_v);
    cudaGetSymbolAddress((void**)&ctx, g_ctx);

    const dim3 blk(256);
    const dim3 gproj(DD / 128, (BB * SDIM) / 128);          // (8, 32)
    const dim3 gsc(SDIM / 128, SDIM / 128, BB * HH);        // (16, 16, 32)
    const dim3 gctx(1, SDIM / 128, BB * HH);                // (1, 16, 32)

    sgemm_nn<<<gproj, blk>>>(query, wq, q, BB * SDIM, DD, DD);
    sgemm_nn<<<gproj, blk>>>(key,   wk, k, BB * SDIM, DD, DD);
    sgemm_nn<<<gproj, blk>>>(value, wv, v, BB * SDIM, DD, DD);

    scores_kernel<<<gsc, blk>>>(q, k, mask, attn);
    softmax_kernel<<<BB * HH * SDIM, blk>>>(attn);
    context_kernel<<<gctx, blk>>>(attn, v, ctx);

    sgemm_nn<<<gproj, blk>>>(ctx, wo, out, BB * SDIM, DD, DD);
}

// round 6
// speedup vs baseline: 1.7143x; 1.7143x over previous
#include <cuda_runtime.h>

// Problem constants
#define BB   2
#define SDIM 2048
#define DD   1024
#define HH   16
#define DKK  64

// Scratch (device globals; no allocations allowed)
__device__ float g_q[BB * SDIM * DD];
__device__ float g_k[BB * SDIM * DD];
__device__ float g_v[BB * SDIM * DD];
__device__ float g_ctx[BB * SDIM * DD];

// ---------------------------------------------------------------------------
// TF32 helpers
// ---------------------------------------------------------------------------
__device__ __forceinline__ unsigned f2tf(float f) {
    unsigned u;
    asm("cvt.rna.tf32.f32 %0, %1;" : "=r"(u) : "f"(f));
    return u;
}

__device__ __forceinline__ void mma_tf32(float* c, const unsigned* a, const unsigned* b) {
    asm volatile(
        "mma.sync.aligned.m16n8k8.row.col.f32.tf32.tf32.f32 "
        "{%0,%1,%2,%3}, {%4,%5,%6,%7}, {%8,%9}, {%0,%1,%2,%3};"
        : "+f"(c[0]), "+f"(c[1]), "+f"(c[2]), "+f"(c[3])
        : "r"(a[0]), "r"(a[1]), "r"(a[2]), "r"(a[3]),
          "r"(b[0]), "r"(b[1]));
}

#define SA 133   // As row stride (scalar stores; odd-ish for bank spread)
#define SB 132   // Bs row stride (16B-aligned for uint4 stores)

// ---------------------------------------------------------------------------
// TF32 GEMM NN: C = A(MxK) * B(KxN), row-major. BM=BN=128, BK=16.
// 256 threads = 8 warps as 4(m) x 2(n); warp tile 32x64; mma m16n8k8.
// ---------------------------------------------------------------------------
__global__ __launch_bounds__(256, 2)
void gemm_tf32_nn(const float* __restrict__ A, const float* __restrict__ B,
                  float* __restrict__ C, int M, int N, int K)
{
    __shared__ unsigned As[16 * SA];   // [k][m]
    __shared__ unsigned Bs[16 * SB];   // [k][n]

    const int tid  = threadIdx.x;
    const int lane = tid & 31;
    const int warp = tid >> 5;
    const int g    = lane >> 2;
    const int tg   = lane & 3;
    const int wm   = (warp >> 1) * 32;
    const int wn   = (warp & 1) * 64;

    const int am = tid >> 1, ak = (tid & 1) * 8;
    const int bk = tid >> 4, bn = (tid & 15) * 8;

    const float* Ap = A + (size_t)(blockIdx.y * 128 + am) * K + ak;
    const float* Bp = B + (size_t)bk * N + blockIdx.x * 128 + bn;

    float4 pa0 = *(const float4*)Ap;
    float4 pa1 = *(const float4*)(Ap + 4);
    float4 pb0 = *(const float4*)Bp;
    float4 pb1 = *(const float4*)(Bp + 4);

    float c[16][4];
    #pragma unroll
    for (int i = 0; i < 16; ++i)
        #pragma unroll
        for (int j = 0; j < 4; ++j) c[i][j] = 0.f;

    const int iters = K >> 4;
    for (int it = 0; it < iters; ++it) {
        As[(ak + 0) * SA + am] = f2tf(pa0.x);
        As[(ak + 1) * SA + am] = f2tf(pa0.y);
        As[(ak + 2) * SA + am] = f2tf(pa0.z);
        As[(ak + 3) * SA + am] = f2tf(pa0.w);
        As[(ak + 4) * SA + am] = f2tf(pa1.x);
        As[(ak + 5) * SA + am] = f2tf(pa1.y);
        As[(ak + 6) * SA + am] = f2tf(pa1.z);
        As[(ak + 7) * SA + am] = f2tf(pa1.w);
        uint4 u0 = make_uint4(f2tf(pb0.x), f2tf(pb0.y), f2tf(pb0.z), f2tf(pb0.w));
        uint4 u1 = make_uint4(f2tf(pb1.x), f2tf(pb1.y), f2tf(pb1.z), f2tf(pb1.w));
        *(uint4*)&Bs[bk * SB + bn]     = u0;
        *(uint4*)&Bs[bk * SB + bn + 4] = u1;
        __syncthreads();

        if (it + 1 < iters) {
            Ap += 16; Bp += (size_t)16 * N;
            pa0 = *(const float4*)Ap;
            pa1 = *(const float4*)(Ap + 4);
            pb0 = *(const float4*)Bp;
            pb1 = *(const float4*)(Bp + 4);
        }

        #pragma unroll
        for (int ks = 0; ks < 2; ++ks) {
            const int kb = ks * 8;
            unsigned a[2][4], b[8][2];
            #pragma unroll
            for (int mi = 0; mi < 2; ++mi) {
                const int m0 = wm + mi * 16 + g;
                a[mi][0] = As[(kb + tg) * SA + m0];
                a[mi][1] = As[(kb + tg) * SA + m0 + 8];
                a[mi][2] = As[(kb + tg + 4) * SA + m0];
                a[mi][3] = As[(kb + tg + 4) * SA + m0 + 8];
            }
            #pragma unroll
            for (int ni = 0; ni < 8; ++ni) {
                const int n0 = wn + ni * 8 + g;
                b[ni][0] = Bs[(kb + tg) * SB + n0];
                b[ni][1] = Bs[(kb + tg + 4) * SB + n0];
            }
            #pragma unroll
            for (int mi = 0; mi < 2; ++mi)
                #pragma unroll
                for (int ni = 0; ni < 8; ++ni)
                    mma_tf32(c[mi * 8 + ni], a[mi], b[ni]);
        }
        __syncthreads();
    }

    #pragma unroll
    for (int mi = 0; mi < 2; ++mi) {
        #pragma unroll
        for (int ni = 0; ni < 8; ++ni) {
            const float* cc = c[mi * 8 + ni];
            const int row = blockIdx.y * 128 + wm + mi * 16 + g;
            const int col = blockIdx.x * 128 + wn + ni * 8 + 2 * tg;
            *(float2*)&C[(size_t)row * N + col]       = make_float2(cc[0], cc[1]);
            *(float2*)&C[(size_t)(row + 8) * N + col] = make_float2(cc[2], cc[3]);
        }
    }
}

// ---------------------------------------------------------------------------
// scores: attn[b,h,i,j] = (q_bh[i].k_bh[j])/8, causal mask applied by index.
// NT GEMM per (b,h). K=64 (BK=16, 4 iters). Tiles with bx>by skipped.
// ---------------------------------------------------------------------------
__global__ __launch_bounds__(256, 2)
void scores_tf32(const float* __restrict__ q, const float* __restrict__ k,
                 float* __restrict__ attn)
{
    const int bx = blockIdx.x;
    const int by = blockIdx.y;
    if (bx > by) return;
    const int z = blockIdx.z;
    const int b = z >> 4;
    const int h = z & 15;

    __shared__ unsigned As[16 * SA];   // [k][i]
    __shared__ unsigned Bs[16 * SA];   // [k][j]

    const int tid  = threadIdx.x;
    const int lane = tid & 31;
    const int warp = tid >> 5;
    const int g    = lane >> 2;
    const int tg   = lane & 3;
    const int wm   = (warp >> 1) * 32;
    const int wn   = (warp & 1) * 64;

    const int r  = tid >> 1, kq = (tid & 1) * 8;

    const float* Ap = q + (size_t)(b * SDIM + by * 128 + r) * DD + h * DKK + kq;
    const float* Bp = k + (size_t)(b * SDIM + bx * 128 + r) * DD + h * DKK + kq;

    float4 pa0 = *(const float4*)Ap;
    float4 pa1 = *(const float4*)(Ap + 4);
    float4 pb0 = *(const float4*)Bp;
    float4 pb1 = *(const float4*)(Bp + 4);

    float c[16][4];
    #pragma unroll
    for (int i = 0; i < 16; ++i)
        #pragma unroll
        for (int j = 0; j < 4; ++j) c[i][j] = 0.f;

    #pragma unroll 1
    for (int it = 0; it < 4; ++it) {
        As[(kq + 0) * SA + r] = f2tf(pa0.x);
        As[(kq + 1) * SA + r] = f2tf(pa0.y);
        As[(kq + 2) * SA + r] = f2tf(pa0.z);
        As[(kq + 3) * SA + r] = f2tf(pa0.w);
        As[(kq + 4) * SA + r] = f2tf(pa1.x);
        As[(kq + 5) * SA + r] = f2tf(pa1.y);
        As[(kq + 6) * SA + r] = f2tf(pa1.z);
        As[(kq + 7) * SA + r] = f2tf(pa1.w);
        Bs[(kq + 0) * SA + r] = f2tf(pb0.x);
        Bs[(kq + 1) * SA + r] = f2tf(pb0.y);
        Bs[(kq + 2) * SA + r] = f2tf(pb0.z);
        Bs[(kq + 3) * SA + r] = f2tf(pb0.w);
        Bs[(kq + 4) * SA + r] = f2tf(pb1.x);
        Bs[(kq + 5) * SA + r] = f2tf(pb1.y);
        Bs[(kq + 6) * SA + r] = f2tf(pb1.z);
        Bs[(kq + 7) * SA + r] = f2tf(pb1.w);
        __syncthreads();

        if (it < 3) {
            Ap += 16; Bp += 16;
            pa0 = *(const float4*)Ap;
            pa1 = *(const float4*)(Ap + 4);
            pb0 = *(const float4*)Bp;
            pb1 = *(const float4*)(Bp + 4);
        }

        #pragma unroll
        for (int ks = 0; ks < 2; ++ks) {
            const int kb = ks * 8;
            unsigned a[2][4], b[8][2];
            #pragma unroll
            for (int mi = 0; mi < 2; ++mi) {
                const int m0 = wm + mi * 16 + g;
                a[mi][0] = As[(kb + tg) * SA + m0];
                a[mi][1] = As[(kb + tg) * SA + m0 + 8];
                a[mi][2] = As[(kb + tg + 4) * SA + m0];
                a[mi][3] = As[(kb + tg + 4) * SA + m0 + 8];
            }
            #pragma unroll
            for (int ni = 0; ni < 8; ++ni) {
                const int n0 = wn + ni * 8 + g;
                b[ni][0] = Bs[(kb + tg) * SA + n0];
                b[ni][1] = Bs[(kb + tg + 4) * SA + n0];
            }
            #pragma unroll
            for (int mi = 0; mi < 2; ++mi)
                #pragma unroll
                for (int ni = 0; ni < 8; ++ni)
                    mma_tf32(c[mi * 8 + ni], a[mi], b[ni]);
        }
        __syncthreads();
    }

    #pragma unroll
    for (int mi = 0; mi < 2; ++mi) {
        #pragma unroll
        for (int ni = 0; ni < 8; ++ni) {
            const float* cc = c[mi * 8 + ni];
            const int i0 = by * 128 + wm + mi * 16 + g;
            const int j0 = bx * 128 + wn + ni * 8 + 2 * tg;
            #pragma unroll
            for (int rr = 0; rr < 2; ++rr) {
                const int i = i0 + rr * 8;
                float2 o;
                o.x = (j0     > i) ? -1e9f : cc[rr * 2 + 0] * 0.125f;
                o.y = (j0 + 1 > i) ? -1e9f : cc[rr * 2 + 1] * 0.125f;
                *(float2*)&attn[((size_t)z * SDIM + i) * SDIM + j0] = o;
            }
        }
    }
}

// ---------------------------------------------------------------------------
// Row softmax in place over computed prefix [0, L); zero-fill [L, S).
// ---------------------------------------------------------------------------
__global__ __launch_bounds__(256)
void softmax_kernel(float* __restrict__ attn)
{
    __shared__ float srow[SDIM];
    __shared__ float redmax[8];
    __shared__ float redsum[8];

    const int r   = blockIdx.x;
    const int i   = r & (SDIM - 1);
    const int L   = ((i >> 7) + 1) << 7;
    const int tid = threadIdx.x;
    float* row = attn + (size_t)r * SDIM;

    float m = -3.4e38f;
    for (int j = tid; j < L; j += 256) {
        float x = row[j];
        srow[j] = x;
        m = fmaxf(m, x);
    }
    #pragma unroll
    for (int o = 16; o; o >>= 1) m = fmaxf(m, __shfl_xor_sync(0xffffffffu, m, o));
    if ((tid & 31) == 0) redmax[tid >> 5] = m;
    __syncthreads();
    if (tid == 0) {
        float t = redmax[0];
        #pragma unroll
        for (int w = 1; w < 8; ++w) t = fmaxf(t, redmax[w]);
        redmax[0] = t;
    }
    __syncthreads();
    const float M = redmax[0];

    float s = 0.f;
    for (int j = tid; j < L; j += 256) {
        float e = __expf(srow[j] - M);
        srow[j] = e;
        s += e;
    }
    #pragma unroll
    for (int o = 16; o; o >>= 1) s += __shfl_xor_sync(0xffffffffu, s, o);
    if ((tid & 31) == 0) redsum[tid >> 5] = s;
    __syncthreads();
    if (tid == 0) {
        float t = 0.f;
        #pragma unroll
        for (int w = 0; w < 8; ++w) t += redsum[w];
        redsum[0] = t;
    }
    __syncthreads();
    const float inv = 1.f / redsum[0];

    for (int j = tid; j < L; j += 256) row[j] = srow[j] * inv;
    for (int j = L + tid; j < SDIM; j += 256) row[j] = 0.f;
}

// ---------------------------------------------------------------------------
// context: ctx[b, i, h*64+c] = sum_j attn[z,i,j] * v[b,j,h*64+c]
// Per (z, by): M-tile 128, N=64, K truncated at i0+128. BK=16.
// 8 warps: warp tile 16x64.
// ---------------------------------------------------------------------------
#define SBC 68
__global__ __launch_bounds__(256, 2)
void context_tf32(const float* __restrict__ attn, const float* __restrict__ v,
                  float* __restrict__ ctx)
{
    const int z = blockIdx.z;
    const int b = z >> 4;
    const int h = z & 15;
    const int i0 = blockIdx.y * 128;

    __shared__ unsigned As[16 * SA];    // [k][i]
    __shared__ unsigned Bs[16 * SBC];   // [k][c]

    const int tid  = threadIdx.x;
    const int lane = tid & 31;
    const int warp = tid >> 5;
    const int g    = lane >> 2;
    const int tg   = lane & 3;

    const int r  = tid >> 1, kq = (tid & 1) * 8;
    const int bk = tid >> 4, bc = (tid & 15) * 4;

    const float* Ap = attn + ((size_t)z * SDIM + i0 + r) * SDIM + kq;
    const float* Bp = v + ((size_t)(b * SDIM) + bk) * DD + h * DKK + bc;

    float4 pa0 = *(const float4*)Ap;
    float4 pa1 = *(const float4*)(Ap + 4);
    float4 pb0 = *(const float4*)Bp;

    float c[8][4];
    #pragma unroll
    for (int i = 0; i < 8; ++i)
        #pragma unroll
        for (int j = 0; j < 4; ++j) c[i][j] = 0.f;

    const int iters = (i0 + 128) >> 4;
    for (int it = 0; it < iters; ++it) {
        As[(kq + 0) * SA + r] = f2tf(pa0.x);
        As[(kq + 1) * SA + r] = f2tf(pa0.y);
        As[(kq + 2) * SA + r] = f2tf(pa0.z);
        As[(kq + 3) * SA + r] = f2tf(pa0.w);
        As[(kq + 4) * SA + r] = f2tf(pa1.x);
        As[(kq + 5) * SA + r] = f2tf(pa1.y);
        As[(kq + 6) * SA + r] = f2tf(pa1.z);
        As[(kq + 7) * SA + r] = f2tf(pa1.w);
        uint4 u0 = make_uint4(f2tf(pb0.x), f2tf(pb0.y), f2tf(pb0.z), f2tf(pb0.w));
        *(uint4*)&Bs[bk * SBC + bc] = u0;
        __syncthreads();

        if (it + 1 < iters) {
            Ap += 16; Bp += (size_t)16 * DD;
            pa0 = *(const float4*)Ap;
            pa1 = *(const float4*)(Ap + 4);
            pb0 = *(const float4*)Bp;
        }

        #pragma unroll
        for (int ks = 0; ks < 2; ++ks) {
            const int kb = ks * 8;
            unsigned a[4], bfrag[8][2];
            const int m0 = warp * 16 + g;
            a[0] = As[(kb + tg) * SA + m0];
            a[1] = As[(kb + tg) * SA + m0 + 8];
            a[2] = As[(kb + tg + 4) * SA + m0];
            a[3] = As[(kb + tg + 4) * SA + m0 + 8];
            #pragma unroll
            for (int ni = 0; ni < 8; ++ni) {
                const int n0 = ni * 8 + g;
                bfrag[ni][0] = Bs[(kb + tg) * SBC + n0];
                bfrag[ni][1] = Bs[(kb + tg + 4) * SBC + n0];
            }
            #pragma unroll
            for (int ni = 0; ni < 8; ++ni)
                mma_tf32(c[ni], a, bfrag[ni]);
        }
        __syncthreads();
    }

    #pragma unroll
    for (int ni = 0; ni < 8; ++ni) {
        const int row = i0 + warp * 16 + g;
        const int col = h * DKK + ni * 8 + 2 * tg;
        *(float2*)&ctx[((size_t)(b * SDIM) + row) * DD + col]     = make_float2(c[ni][0], c[ni][1]);
        *(float2*)&ctx[((size_t)(b * SDIM) + row + 8) * DD + col] = make_float2(c[ni][2], c[ni][3]);
    }
}

// ---------------------------------------------------------------------------
extern "C" void kernel_launch(void* const* d_in, const int* in_sizes, int n_in,
                              void* d_out, int out_size)
{
    const float* query = (const float*)d_in[0];
    const float* key   = (const float*)d_in[1];
    const float* value = (const float*)d_in[2];
    const float* wq    = (const float*)d_in[4];
    const float* wk    = (const float*)d_in[5];
    const float* wv    = (const float*)d_in[6];
    const float* wo    = (const float*)d_in[7];

    float* out  = (float*)d_out;
    float* attn = out + (size_t)BB * SDIM * DD;

    float *q, *k, *v, *ctx;
    cudaGetSymbolAddress((void**)&q,   g_q);
    cudaGetSymbolAddress((void**)&k,   g_k);
    cudaGetSymbolAddress((void**)&v,   g_v);
    cudaGetSymbolAddress((void**)&ctx, g_ctx);

    const dim3 blk(256);
    const dim3 gproj(DD / 128, (BB * SDIM) / 128);       // (8, 32)
    const dim3 gsc(SDIM / 128, SDIM / 128, BB * HH);     // (16, 16, 32)
    const dim3 gctx(1, SDIM / 128, BB * HH);             // (1, 16, 32)

    gemm_tf32_nn<<<gproj, blk>>>(query, wq, q, BB * SDIM, DD, DD);
    gemm_tf32_nn<<<gproj, blk>>>(key,   wk, k, BB * SDIM, DD, DD);
    gemm_tf32_nn<<<gproj, blk>>>(value, wv, v, BB * SDIM, DD, DD);

    scores_tf32<<<gsc, blk>>>(q, k, attn);
    softmax_kernel<<<BB * HH * SDIM, blk>>>(attn);
    context_tf32<<<gctx, blk>>>(attn, v, ctx);

    gemm_tf32_nn<<<gproj, blk>>>(ctx, wo, out, BB * SDIM, DD, DD);
}

// round 7
// speedup vs baseline: 2.0691x; 1.2070x over previous
#include <cuda_runtime.h>

// Problem constants
#define BB   2
#define SDIM 2048
#define DD   1024
#define HH   16
#define DKK  64

// Scratch (device globals; no allocations allowed)
__device__ float g_q[BB * SDIM * DD];
__device__ float g_k[BB * SDIM * DD];
__device__ float g_v[BB * SDIM * DD];
__device__ float g_ctx[BB * SDIM * DD];

// ---------------------------------------------------------------------------
// TF32 helpers
// ---------------------------------------------------------------------------
__device__ __forceinline__ unsigned f2tf(float f) {
    unsigned u;
    asm("cvt.rna.tf32.f32 %0, %1;" : "=r"(u) : "f"(f));
    return u;
}

template <bool C>
__device__ __forceinline__ unsigned tfbits(float f) {
    return C ? f2tf(f) : __float_as_uint(f);
}

__device__ __forceinline__ void mma4(float* c,
                                     unsigned a0, unsigned a1, unsigned a2, unsigned a3,
                                     unsigned b0, unsigned b1) {
    asm volatile(
        "mma.sync.aligned.m16n8k8.row.col.f32.tf32.tf32.f32 "
        "{%0,%1,%2,%3}, {%4,%5,%6,%7}, {%8,%9}, {%0,%1,%2,%3};"
        : "+f"(c[0]), "+f"(c[1]), "+f"(c[2]), "+f"(c[3])
        : "r"(a0), "r"(a1), "r"(a2), "r"(a3), "r"(b0), "r"(b1));
}

// Paired-k shared layouts (BK = 16).
// A-style: word = ((k>>3)*4 + (k&3))*264 + m*2 + ((k>>2)&1).
//   64-bit load at ((kb>>3)*4 + tg)*264 + m*2 -> {A[m][kb+tg], A[m][kb+tg+4]}.
// B-style adds XOR swizzle on w = n*2 + ((k>>2)&1):  w ^= ((w>>5)&7)<<1.
#define PSTR 264   // row stride (words), 264 % 32 == 8
#define PSTRC 136  // context-B row stride (N=64), 136 % 32 == 8

// A-style writer: thread holds 8 consecutive k (= ak..ak+7) for one m.
template <bool C>
__device__ __forceinline__ void store_apair(unsigned* S, int ak, int m,
                                            float4 p0, float4 p1) {
    unsigned* b = S + ((ak >> 3) * 4) * PSTR + m * 2;
    b[0]            = tfbits<C>(p0.x);
    b[PSTR]         = tfbits<C>(p0.y);
    b[2 * PSTR]     = tfbits<C>(p0.z);
    b[3 * PSTR]     = tfbits<C>(p0.w);
    b[1]            = tfbits<C>(p1.x);
    b[PSTR + 1]     = tfbits<C>(p1.y);
    b[2 * PSTR + 1] = tfbits<C>(p1.z);
    b[3 * PSTR + 1] = tfbits<C>(p1.w);
}

__device__ __forceinline__ int bsw(int n, int q) {
    int w = n * 2 + q;
    w ^= ((w >> 5) & 7) << 1;
    return w;
}

// ---------------------------------------------------------------------------
// TF32 GEMM NN: C = A(MxK) * B(KxN), row-major. BM=BN=128, BK=16.
// 8 warps as 4(m) x 2(n); warp tile 32x64.
// ---------------------------------------------------------------------------
template <bool CA, bool CB, bool RO>
__global__ __launch_bounds__(256, 2)
void gemm_tf32_nn(const float* __restrict__ A, const float* __restrict__ B,
                  float* __restrict__ C, int M, int N, int K)
{
    __shared__ unsigned As[8 * PSTR];
    __shared__ unsigned Bs[8 * PSTR];

    const int tid  = threadIdx.x;
    const int lane = tid & 31;
    const int warp = tid >> 5;
    const int g    = lane >> 2;
    const int tg   = lane & 3;
    const int wm   = (warp >> 1) * 32;
    const int wn   = (warp & 1) * 64;

    const int am = tid >> 1, ak = (tid & 1) * 8;
    const int bk = tid >> 4, bn = (tid & 15) * 8;
    const int bp = ((bk >> 3) * 4 + (bk & 3)) * PSTR;
    const int bq = (bk >> 2) & 1;

    const float* Ap = A + (size_t)(blockIdx.y * 128 + am) * K + ak;
    const float* Bp = B + (size_t)bk * N + blockIdx.x * 128 + bn;

    float4 pa0 = *(const float4*)Ap;
    float4 pa1 = *(const float4*)(Ap + 4);
    float4 pb0 = *(const float4*)Bp;
    float4 pb1 = *(const float4*)(Bp + 4);

    float c[16][4];
    #pragma unroll
    for (int i = 0; i < 16; ++i)
        #pragma unroll
        for (int j = 0; j < 4; ++j) c[i][j] = 0.f;

    const int iters = K >> 4;
    for (int it = 0; it < iters; ++it) {
        store_apair<CA>(As, ak, am, pa0, pa1);
        Bs[bp + bsw(bn + 0, bq)] = tfbits<CB>(pb0.x);
        Bs[bp + bsw(bn + 1, bq)] = tfbits<CB>(pb0.y);
        Bs[bp + bsw(bn + 2, bq)] = tfbits<CB>(pb0.z);
        Bs[bp + bsw(bn + 3, bq)] = tfbits<CB>(pb0.w);
        Bs[bp + bsw(bn + 4, bq)] = tfbits<CB>(pb1.x);
        Bs[bp + bsw(bn + 5, bq)] = tfbits<CB>(pb1.y);
        Bs[bp + bsw(bn + 6, bq)] = tfbits<CB>(pb1.z);
        Bs[bp + bsw(bn + 7, bq)] = tfbits<CB>(pb1.w);
        __syncthreads();

        if (it + 1 < iters) {
            Ap += 16; Bp += (size_t)16 * N;
            pa0 = *(const float4*)Ap;
            pa1 = *(const float4*)(Ap + 4);
            pb0 = *(const float4*)Bp;
            pb1 = *(const float4*)(Bp + 4);
        }

        #pragma unroll
        for (int ks = 0; ks < 2; ++ks) {
            const unsigned* Ar = As + (ks * 4 + tg) * PSTR;
            const unsigned* Br = Bs + (ks * 4 + tg) * PSTR;
            uint2 a0 = *(const uint2*)(Ar + (wm + g) * 2);
            uint2 a1 = *(const uint2*)(Ar + (wm + g + 8) * 2);
            uint2 a2 = *(const uint2*)(Ar + (wm + 16 + g) * 2);
            uint2 a3 = *(const uint2*)(Ar + (wm + 24 + g) * 2);
            #pragma unroll
            for (int ni = 0; ni < 8; ++ni) {
                int w = (wn + ni * 8 + g) * 2;
                w ^= ((w >> 5) & 7) << 1;
                uint2 bb = *(const uint2*)(Br + w);
                mma4(c[ni],     a0.x, a1.x, a0.y, a1.y, bb.x, bb.y);
                mma4(c[8 + ni], a2.x, a3.x, a2.y, a3.y, bb.x, bb.y);
            }
        }
        __syncthreads();
    }

    #pragma unroll
    for (int mi = 0; mi < 2; ++mi) {
        #pragma unroll
        for (int ni = 0; ni < 8; ++ni) {
            const float* cc = c[mi * 8 + ni];
            const int row = blockIdx.y * 128 + wm + mi * 16 + g;
            const int col = blockIdx.x * 128 + wn + ni * 8 + 2 * tg;
            float v0 = cc[0], v1 = cc[1], v2 = cc[2], v3 = cc[3];
            if (RO) {
                v0 = __uint_as_float(f2tf(v0));
                v1 = __uint_as_float(f2tf(v1));
                v2 = __uint_as_float(f2tf(v2));
                v3 = __uint_as_float(f2tf(v3));
            }
            *(float2*)&C[(size_t)row * N + col]       = make_float2(v0, v1);
            *(float2*)&C[(size_t)(row + 8) * N + col] = make_float2(v2, v3);
        }
    }
}

// ---------------------------------------------------------------------------
// scores: attn[b,h,i,j] = (q_bh[i].k_bh[j])/8, causal mask by index.
// q, k are pre-rounded tf32 (no cvt anywhere). Both operands A-style pairs.
// ---------------------------------------------------------------------------
__global__ __launch_bounds__(256, 2)
void scores_tf32(const float* __restrict__ q, const float* __restrict__ k,
                 float* __restrict__ attn)
{
    const int bx = blockIdx.x;
    const int by = blockIdx.y;
    if (bx > by) return;
    const int z = blockIdx.z;
    const int b = z >> 4;
    const int h = z & 15;

    __shared__ unsigned As[8 * PSTR];
    __shared__ unsigned Bs[8 * PSTR];

    const int tid  = threadIdx.x;
    const int lane = tid & 31;
    const int warp = tid >> 5;
    const int g    = lane >> 2;
    const int tg   = lane & 3;
    const int wm   = (warp >> 1) * 32;
    const int wn   = (warp & 1) * 64;

    const int r = tid >> 1, kq = (tid & 1) * 8;

    const float* Ap = q + (size_t)(b * SDIM + by * 128 + r) * DD + h * DKK + kq;
    const float* Bp = k + (size_t)(b * SDIM + bx * 128 + r) * DD + h * DKK + kq;

    float4 pa0 = *(const float4*)Ap;
    float4 pa1 = *(const float4*)(Ap + 4);
    float4 pb0 = *(const float4*)Bp;
    float4 pb1 = *(const float4*)(Bp + 4);

    float c[16][4];
    #pragma unroll
    for (int i = 0; i < 16; ++i)
        #pragma unroll
        for (int j = 0; j < 4; ++j) c[i][j] = 0.f;

    for (int it = 0; it < 4; ++it) {
        store_apair<false>(As, kq, r, pa0, pa1);
        store_apair<false>(Bs, kq, r, pb0, pb1);
        __syncthreads();

        if (it < 3) {
            Ap += 16; Bp += 16;
            pa0 = *(const float4*)Ap;
            pa1 = *(const float4*)(Ap + 4);
            pb0 = *(const float4*)Bp;
            pb1 = *(const float4*)(Bp + 4);
        }

        #pragma unroll
        for (int ks = 0; ks < 2; ++ks) {
            const unsigned* Ar = As + (ks * 4 + tg) * PSTR;
            const unsigned* Br = Bs + (ks * 4 + tg) * PSTR;
            uint2 a0 = *(const uint2*)(Ar + (wm + g) * 2);
            uint2 a1 = *(const uint2*)(Ar + (wm + g + 8) * 2);
            uint2 a2 = *(const uint2*)(Ar + (wm + 16 + g) * 2);
            uint2 a3 = *(const uint2*)(Ar + (wm + 24 + g) * 2);
            #pragma unroll
            for (int ni = 0; ni < 8; ++ni) {
                uint2 bb = *(const uint2*)(Br + (wn + ni * 8 + g) * 2);
                mma4(c[ni],     a0.x, a1.x, a0.y, a1.y, bb.x, bb.y);
                mma4(c[8 + ni], a2.x, a3.x, a2.y, a3.y, bb.x, bb.y);
            }
        }
        __syncthreads();
    }

    #pragma unroll
    for (int mi = 0; mi < 2; ++mi) {
        #pragma unroll
        for (int ni = 0; ni < 8; ++ni) {
            const float* cc = c[mi * 8 + ni];
            const int i0 = by * 128 + wm + mi * 16 + g;
            const int j0 = bx * 128 + wn + ni * 8 + 2 * tg;
            #pragma unroll
            for (int rr = 0; rr < 2; ++rr) {
                const int i = i0 + rr * 8;
                float2 o;
                o.x = (j0     > i) ? -1e9f : cc[rr * 2 + 0] * 0.125f;
                o.y = (j0 + 1 > i) ? -1e9f : cc[rr * 2 + 1] * 0.125f;
                *(float2*)&attn[((size_t)z * SDIM + i) * SDIM + j0] = o;
            }
        }
    }
}

// ---------------------------------------------------------------------------
// Row softmax in place over computed prefix [0, L); zero-fill [L, S).
// Row cached in registers (max 2048 / 256 = 8 per thread).
// ---------------------------------------------------------------------------
__global__ __launch_bounds__(256)
void softmax_kernel(float* __restrict__ attn)
{
    __shared__ float redmax[8];
    __shared__ float redsum[8];

    const int r   = blockIdx.x;
    const int i   = r & (SDIM - 1);
    const int L   = ((i >> 7) + 1) << 7;
    const int tid = threadIdx.x;
    float* row = attn + (size_t)r * SDIM;

    float x[8];
    float m = -3.4e38f;
    #pragma unroll
    for (int t = 0; t < 8; ++t) {
        const int j = tid + t * 256;
        if (j < L) { x[t] = row[j]; m = fmaxf(m, x[t]); }
    }
    #pragma unroll
    for (int o = 16; o; o >>= 1) m = fmaxf(m, __shfl_xor_sync(0xffffffffu, m, o));
    if ((tid & 31) == 0) redmax[tid >> 5] = m;
    __syncthreads();
    if (tid == 0) {
        float t = redmax[0];
        #pragma unroll
        for (int w = 1; w < 8; ++w) t = fmaxf(t, redmax[w]);
        redmax[0] = t;
    }
    __syncthreads();
    const float M = redmax[0];

    float s = 0.f;
    #pragma unroll
    for (int t = 0; t < 8; ++t) {
        const int j = tid + t * 256;
        if (j < L) { x[t] = __expf(x[t] - M); s += x[t]; }
    }
    #pragma unroll
    for (int o = 16; o; o >>= 1) s += __shfl_xor_sync(0xffffffffu, s, o);
    if ((tid & 31) == 0) redsum[tid >> 5] = s;
    __syncthreads();
    if (tid == 0) {
        float t = 0.f;
        #pragma unroll
        for (int w = 0; w < 8; ++w) t += redsum[w];
        redsum[0] = t;
    }
    __syncthreads();
    const float inv = 1.f / redsum[0];

    #pragma unroll
    for (int t = 0; t < 8; ++t) {
        const int j = tid + t * 256;
        if (j < L) row[j] = x[t] * inv;
    }
    for (int j = L + tid; j < SDIM; j += 256) row[j] = 0.f;
}

// ---------------------------------------------------------------------------
// context: ctx[b, i, h*64+c] = sum_j attn[z,i,j] * v[b,j,h*64+c]
// attn needs cvt (fp32 weights); v is pre-rounded. Output pre-rounded (feeds
// the out-projection with CA=false).
// ---------------------------------------------------------------------------
__global__ __launch_bounds__(256, 2)
void context_tf32(const float* __restrict__ attn, const float* __restrict__ v,
                  float* __restrict__ ctx)
{
    const int z = blockIdx.z;
    const int b = z >> 4;
    const int h = z & 15;
    const int i0 = blockIdx.y * 128;

    __shared__ unsigned As[8 * PSTR];
    __shared__ unsigned Bs[8 * PSTRC];

    const int tid  = threadIdx.x;
    const int lane = tid & 31;
    const int warp = tid >> 5;
    const int g    = lane >> 2;
    const int tg   = lane & 3;

    const int r  = tid >> 1, kq = (tid & 1) * 8;
    const int bk = tid >> 4, bc = (tid & 15) * 4;
    const int bp = ((bk >> 3) * 4 + (bk & 3)) * PSTRC;
    const int bq = (bk >> 2) & 1;

    const float* Ap = attn + ((size_t)z * SDIM + i0 + r) * SDIM + kq;
    const float* Bp = v + ((size_t)(b * SDIM) + bk) * DD + h * DKK + bc;

    float4 pa0 = *(const float4*)Ap;
    float4 pa1 = *(const float4*)(Ap + 4);
    float4 pb0 = *(const float4*)Bp;

    float c[8][4];
    #pragma unroll
    for (int i = 0; i < 8; ++i)
        #pragma unroll
        for (int j = 0; j < 4; ++j) c[i][j] = 0.f;

    const int iters = (i0 + 128) >> 4;
    for (int it = 0; it < iters; ++it) {
        store_apair<true>(As, kq, r, pa0, pa1);
        Bs[bp + bsw(bc + 0, bq)] = __float_as_uint(pb0.x);
        Bs[bp + bsw(bc + 1, bq)] = __float_as_uint(pb0.y);
        Bs[bp + bsw(bc + 2, bq)] = __float_as_uint(pb0.z);
        Bs[bp + bsw(bc + 3, bq)] = __float_as_uint(pb0.w);
        __syncthreads();

        if (it + 1 < iters) {
            Ap += 16; Bp += (size_t)16 * DD;
            pa0 = *(const float4*)Ap;
            pa1 = *(const float4*)(Ap + 4);
            pb0 = *(const float4*)Bp;
        }

        #pragma unroll
        for (int ks = 0; ks < 2; ++ks) {
            const unsigned* Ar = As + (ks * 4 + tg) * PSTR;
            const unsigned* Br = Bs + (ks * 4 + tg) * PSTRC;
            const int m0 = warp * 16 + g;
            uint2 a0 = *(const uint2*)(Ar + m0 * 2);
            uint2 a1 = *(const uint2*)(Ar + (m0 + 8) * 2);
            #pragma unroll
            for (int ni = 0; ni < 8; ++ni) {
                int w = (ni * 8 + g) * 2;
                w ^= ((w >> 5) & 7) << 1;
                uint2 bb = *(const uint2*)(Br + w);
                mma4(c[ni], a0.x, a1.x, a0.y, a1.y, bb.x, bb.y);
            }
        }
        __syncthreads();
    }

    #pragma unroll
    for (int ni = 0; ni < 8; ++ni) {
        const int row = i0 + warp * 16 + g;
        const int col = h * DKK + ni * 8 + 2 * tg;
        float v0 = __uint_as_float(f2tf(c[ni][0]));
        float v1 = __uint_as_float(f2tf(c[ni][1]));
        float v2 = __uint_as_float(f2tf(c[ni][2]));
        float v3 = __uint_as_float(f2tf(c[ni][3]));
        *(float2*)&ctx[((size_t)(b * SDIM) + row) * DD + col]     = make_float2(v0, v1);
        *(float2*)&ctx[((size_t)(b * SDIM) + row + 8) * DD + col] = make_float2(v2, v3);
    }
}

// ---------------------------------------------------------------------------
extern "C" void kernel_launch(void* const* d_in, const int* in_sizes, int n_in,
                              void* d_out, int out_size)
{
    const float* query = (const float*)d_in[0];
    const float* key   = (const float*)d_in[1];
    const float* value = (const float*)d_in[2];
    const float* wq    = (const float*)d_in[4];
    const float* wk    = (const float*)d_in[5];
    const float* wv    = (const float*)d_in[6];
    const float* wo    = (const float*)d_in[7];

    float* out  = (float*)d_out;
    float* attn = out + (size_t)BB * SDIM * DD;

    float *q, *k, *v, *ctx;
    cudaGetSymbolAddress((void**)&q,   g_q);
    cudaGetSymbolAddress((void**)&k,   g_k);
    cudaGetSymbolAddress((void**)&v,   g_v);
    cudaGetSymbolAddress((void**)&ctx, g_ctx);

    const dim3 blk(256);
    const dim3 gproj(DD / 128, (BB * SDIM) / 128);       // (8, 32)
    const dim3 gsc(SDIM / 128, SDIM / 128, BB * HH);     // (16, 16, 32)
    const dim3 gctx(1, SDIM / 128, BB * HH);             // (1, 16, 32)

    // Projections: cvt both operands, pre-round outputs to tf32.
    gemm_tf32_nn<true, true, true><<<gproj, blk>>>(query, wq, q, BB * SDIM, DD, DD);
    gemm_tf32_nn<true, true, true><<<gproj, blk>>>(key,   wk, k, BB * SDIM, DD, DD);
    gemm_tf32_nn<true, true, true><<<gproj, blk>>>(value, wv, v, BB * SDIM, DD, DD);

    scores_tf32<<<gsc, blk>>>(q, k, attn);
    softmax_kernel<<<BB * HH * SDIM, blk>>>(attn);
    context_tf32<<<gctx, blk>>>(attn, v, ctx);

    // Out projection: ctx already tf32 (CA=false), exact fp32 output (RO=false).
    gemm_tf32_nn<false, true, false><<<gproj, blk>>>(ctx, wo, out, BB * SDIM, DD, DD);
}